// round 12
// baseline (speedup 1.0000x reference)
#include <cuda_runtime.h>
#include <cuda_bf16.h>
#include <cstdint>
#include <math.h>

// Problem constants: B=32, S=64, E=256, H=4, D=64
#define NROWS 2048
#define EDIM  256
#define NQKV  768
#define NH    4

// ---------------- scratch (__device__ globals, no allocs) -------------------
__device__ __nv_bfloat16 g_Bhi[NQKV * EDIM],  g_Blo[NQKV * EDIM];    // exp(Wqkv) [n][k]
__device__ __nv_bfloat16 g_Chi[EDIM * EDIM],  g_Clo[EDIM * EDIM];    // exp(Wo)   [n][k]
__device__ __nv_bfloat16 g_EOhi[NROWS * EDIM], g_EOlo[NROWS * EDIM]; // exp(attn out)

// ---------------- helpers (base ISA only — sm_103 non-variant) --------------
__device__ __forceinline__ uint32_t smem_u32(const void* p) {
    uint32_t a;
    asm("{ .reg .u64 t; cvta.to.shared.u64 t, %1; cvt.u32.u64 %0, t; }"
        : "=r"(a) : "l"(p));
    return a;
}
__device__ __forceinline__ void ldsm_x4(uint32_t* r, uint32_t addr) {
    asm volatile("ldmatrix.sync.aligned.m8n8.x4.shared.b16 {%0,%1,%2,%3}, [%4];"
                 : "=r"(r[0]), "=r"(r[1]), "=r"(r[2]), "=r"(r[3]) : "r"(addr));
}
__device__ __forceinline__ void mma16816(float* d, const uint32_t* a,
                                         uint32_t b0, uint32_t b1) {
    asm volatile(
        "mma.sync.aligned.m16n8k16.row.col.f32.bf16.bf16.f32 "
        "{%0,%1,%2,%3}, {%4,%5,%6,%7}, {%8,%9}, {%0,%1,%2,%3};"
        : "+f"(d[0]), "+f"(d[1]), "+f"(d[2]), "+f"(d[3])
        : "r"(a[0]), "r"(a[1]), "r"(a[2]), "r"(a[3]), "r"(b0), "r"(b1));
}
__device__ __forceinline__ void cp16(uint32_t s, const void* g) {
    asm volatile("cp.async.cg.shared.global [%0], [%1], 16;" :: "r"(s), "l"(g));
}
#define CP_COMMIT() asm volatile("cp.async.commit_group;" ::: "memory")
#define CP_WAIT1()  asm volatile("cp.async.wait_group 1;" ::: "memory")
#define CP_WAIT0()  asm volatile("cp.async.wait_group 0;" ::: "memory")

// exp + hi/lo split of 4 floats -> packed bf16x4 (uint2 each)
__device__ __forceinline__ void exp_split4(const float4& v, uint2& hi, uint2& lo) {
    float e[4] = {__expf(v.x), __expf(v.y), __expf(v.z), __expf(v.w)};
    __nv_bfloat16 h[4], l[4];
    #pragma unroll
    for (int j = 0; j < 4; ++j) {
        h[j] = __float2bfloat16(e[j]);
        l[j] = __float2bfloat16(e[j] - __bfloat162float(h[j]));
    }
    __nv_bfloat162 h0 = __halves2bfloat162(h[0], h[1]);
    __nv_bfloat162 h1 = __halves2bfloat162(h[2], h[3]);
    __nv_bfloat162 l0 = __halves2bfloat162(l[0], l[1]);
    __nv_bfloat162 l1 = __halves2bfloat162(l[2], l[3]);
    hi.x = *(uint32_t*)&h0; hi.y = *(uint32_t*)&h1;
    lo.x = *(uint32_t*)&l0; lo.y = *(uint32_t*)&l1;
}

// ---------------------------------------------------------------------------
// Prep kernels: exp + bf16 hi/lo split of the weights.
//   k_prep_qkv : Wq/Wk/Wv -> g_Bhi/g_Blo   (feeds k_qkv_attn)
//   k_prep_o   : Wo       -> g_Chi/g_Clo   (feeds k_ogemm; runs on 2nd stream)
// ---------------------------------------------------------------------------
__global__ void k_prep_qkv(const float* __restrict__ Wq, const float* __restrict__ Wk,
                           const float* __restrict__ Wv)
{
    int q = blockIdx.x * blockDim.x + threadIdx.x;   // quad index < 49152
    int idx = q * 4;
    int n = idx / EDIM, k = idx - n * EDIM;
    const float* W = (n < 256) ? Wq : ((n < 512) ? Wk : Wv);
    uint2 h2, l2;
    exp_split4(*(const float4*)&W[(n & 255) * EDIM + k], h2, l2);
    *(uint2*)&g_Bhi[idx] = h2;
    *(uint2*)&g_Blo[idx] = l2;
}

__global__ void k_prep_o(const float* __restrict__ Wo)
{
    int q = blockIdx.x * blockDim.x + threadIdx.x;   // quad index < 16384
    int idx = q * 4;
    uint2 h2, l2;
    exp_split4(*(const float4*)&Wo[idx], h2, l2);
    *(uint2*)&g_Chi[idx] = h2;
    *(uint2*)&g_Clo[idx] = l2;
}

// ---------------------------------------------------------------------------
// FUSED exp(x) + QKV GEMM + attention. CTA = (head h, batch b), grid (4, 32).
// ---------------------------------------------------------------------------
#define LDTA 264                           // A row stride (bf16 elems)
#define A_ARR (64 * LDTA * 2)              // 33792 B
#define LDT 72                             // B row stride
#define B_ARR (64 * LDT * 2)               // 9216 B
#define OFF_A0 0
#define OFF_A1 A_ARR
#define OFF_B  (2 * A_ARR)                 // 67584
#define OFF_P  (OFF_B + 6 * B_ARR)         // 122880
#define OFF_V  (OFF_P + 64 * 65 * 4)       // 139520
#define OFF_INV (OFF_V + 64 * 68 * 4)      // 156928
#define FUSED_SMEM (OFF_INV + 256)         // 157184

__global__ void __launch_bounds__(256) k_qkv_attn(
    const float* __restrict__ x,
    const __nv_bfloat16* __restrict__ Bhi, const __nv_bfloat16* __restrict__ Blo,
    const float* __restrict__ bq, const float* __restrict__ bk,
    const float* __restrict__ bv)
{
    extern __shared__ char smem[];
    const uint32_t sbase = smem_u32(smem);
    float* P   = (float*)(smem + OFF_P);   // [64][65]
    float* V   = (float*)(smem + OFF_V);   // [64][68]
    float* inv = (float*)(smem + OFF_INV);

    const int tid  = threadIdx.x;
    const int lane = tid & 31;
    const int warp = tid >> 5;
    const int wm   = (warp & 1) * 32;
    const int wn   = (warp >> 1) * 16;
    const int h = blockIdx.x;
    const int b = blockIdx.y;
    const int m0 = b * 64;

    // B prefetch: chunk it (region = it>>2, kc = it&3), stage it%3
    auto prefB = [&](int it) {
        const int reg = it >> 2, kc = it & 3;
        const int brow0 = reg * 256 + h * 64;
        const uint32_t s0 = sbase + OFF_B + (uint32_t)(it % 3) * (2 * B_ARR);
        #pragma unroll
        for (int i = 0; i < 2; ++i) {
            int c = tid + 256 * i;
            int r = c >> 3, k8 = (c & 7) * 8;
            uint32_t so = (r * LDT + k8) * 2;
            cp16(s0 + so,         &Bhi[(brow0 + r) * EDIM + kc * 64 + k8]);
            cp16(s0 + B_ARR + so, &Blo[(brow0 + r) * EDIM + kc * 64 + k8]);
        }
        CP_COMMIT();
    };
    prefB(0); prefB(1);

    // ---- prolog: LDG x fp32, exp+split, STS into A hi/lo tiles ------------
    #pragma unroll
    for (int i = 0; i < 8; ++i) {
        int c = tid + 256 * i;
        int r = c >> 5, k8 = (c & 31) * 8;
        const float4* xs = (const float4*)&x[(m0 + r) * EDIM + k8];
        float4 v0 = xs[0], v1 = xs[1];
        uint2 h0, l0, h1, l1;
        exp_split4(v0, h0, l0);
        exp_split4(v1, h1, l1);
        uint32_t so = (r * LDTA + k8) * 2;
        *(uint4*)(smem + OFF_A0 + so) = make_uint4(h0.x, h0.y, h1.x, h1.y);
        *(uint4*)(smem + OFF_A1 + so) = make_uint4(l0.x, l0.y, l1.x, l1.y);
    }

    // ldmatrix base offsets
    uint32_t aOff[2];
    #pragma unroll
    for (int mf = 0; mf < 2; ++mf)
        aOff[mf] = (uint32_t)(((wm + mf * 16 + (lane & 15)) * LDTA + (lane >> 4) * 8) * 2);
    const uint32_t bOff = (uint32_t)(((wn + (lane >> 4) * 8 + (lane & 7)) * LDT
                                      + ((lane >> 3) & 1) * 8) * 2);

    float acc[2][2][4];
    #pragma unroll
    for (int mf = 0; mf < 2; ++mf)
        #pragma unroll
        for (int nf = 0; nf < 2; ++nf)
            #pragma unroll
            for (int j = 0; j < 4; ++j) acc[mf][nf][j] = 0.f;

    for (int it = 0; it < 12; ++it) {
        if (it < 11) CP_WAIT1(); else CP_WAIT0();
        __syncthreads();                 // publishes A STS (it==0) + B chunk it
        if (it < 10) prefB(it + 2);

        const int kc = it & 3;
        const uint32_t sB = sbase + OFF_B + (uint32_t)(it % 3) * (2 * B_ARR);
        #pragma unroll
        for (int ks = 0; ks < 4; ++ks) {
            const uint32_t aByte = (uint32_t)((kc * 64 + ks * 16) * 2);
            const uint32_t kByte = ks * 32;
            uint32_t ah[2][4], al[2][4], bh[4], bl[4];
            #pragma unroll
            for (int mf = 0; mf < 2; ++mf) {
                ldsm_x4(ah[mf], sbase + OFF_A0 + aOff[mf] + aByte);
                ldsm_x4(al[mf], sbase + OFF_A1 + aOff[mf] + aByte);
            }
            ldsm_x4(bh, sB + bOff + kByte);
            ldsm_x4(bl, sB + B_ARR + bOff + kByte);
            #pragma unroll
            for (int mf = 0; mf < 2; ++mf) {
                #pragma unroll
                for (int nf = 0; nf < 2; ++nf) {
                    mma16816(acc[mf][nf], ah[mf], bh[nf * 2], bh[nf * 2 + 1]);
                    mma16816(acc[mf][nf], ah[mf], bl[nf * 2], bl[nf * 2 + 1]);
                    mma16816(acc[mf][nf], al[mf], bh[nf * 2], bh[nf * 2 + 1]);
                }
            }
        }

        // region boundary epilogues (same thread owns same (s,d) across regions)
        if (kc == 3) {
            const int reg = it >> 2;
            #pragma unroll
            for (int mf = 0; mf < 2; ++mf)
                #pragma unroll
                for (int nf = 0; nf < 2; ++nf)
                    #pragma unroll
                    for (int j = 0; j < 4; ++j) {
                        int s = wm + mf * 16 + (lane >> 2) + (j >> 1) * 8;
                        int d = wn + nf * 8 + (lane & 3) * 2 + (j & 1);
                        float v = acc[mf][nf][j];
                        if (reg == 0)      P[s * 65 + d]  = v * __expf(bq[h * 64 + d]);
                        else if (reg == 1) P[s * 65 + d] *= v * __expf(bk[h * 64 + d]);
                        else               V[s * 68 + d]  = __logf(v) + bv[h * 64 + d];
                        acc[mf][nf][j] = 0.f;
                    }
        }
    }
    __syncthreads();

    // ---- rowsum -> inv -----------------------------------------------------
    if (tid < 64) {
        float s = 0.f;
        #pragma unroll
        for (int j = 0; j < 64; ++j) s += P[tid * 65 + j];
        inv[tid] = 1.0f / s;
    }
    __syncthreads();

    // ---- out = (P * inv) @ V ; EO = exp(out) -------------------------------
    const int tx = tid & 15;
    const int ty = tid >> 4;
    float oacc[4][4] = {};
    #pragma unroll 4
    for (int d = 0; d < 64; ++d) {
        float p0 = P[(4 * ty + 0) * 65 + d];
        float p1 = P[(4 * ty + 1) * 65 + d];
        float p2 = P[(4 * ty + 2) * 65 + d];
        float p3 = P[(4 * ty + 3) * 65 + d];
        float4 v4 = *(const float4*)&V[d * 68 + 4 * tx];
        oacc[0][0] += p0 * v4.x; oacc[0][1] += p0 * v4.y;
        oacc[0][2] += p0 * v4.z; oacc[0][3] += p0 * v4.w;
        oacc[1][0] += p1 * v4.x; oacc[1][1] += p1 * v4.y;
        oacc[1][2] += p1 * v4.z; oacc[1][3] += p1 * v4.w;
        oacc[2][0] += p2 * v4.x; oacc[2][1] += p2 * v4.y;
        oacc[2][2] += p2 * v4.z; oacc[2][3] += p2 * v4.w;
        oacc[3][0] += p3 * v4.x; oacc[3][1] += p3 * v4.y;
        oacc[3][2] += p3 * v4.z; oacc[3][3] += p3 * v4.w;
    }
    #pragma unroll
    for (int r = 0; r < 4; ++r) {
        float iv = inv[4 * ty + r];
        int grow = b * 64 + 4 * ty + r;
        #pragma unroll
        for (int c = 0; c < 4; ++c) {
            float eo = __expf(oacc[r][c] * iv);
            __nv_bfloat16 hb = __float2bfloat16(eo);
            int gi = grow * EDIM + h * 64 + 4 * tx + c;
            g_EOhi[gi] = hb;
            g_EOlo[gi] = __float2bfloat16(eo - __bfloat162float(hb));
        }
    }
}

// ---------------------------------------------------------------------------
// Output projection GEMM: out = log(EO @ exp(Wo)) + bo.
// ---------------------------------------------------------------------------
#define OARR (64 * LDT * 2)                // 9216
#define OSTG (4 * OARR)                    // 36864
#define OSM  (2 * OSTG)                    // 73728

__global__ void __launch_bounds__(256) k_ogemm(
    const __nv_bfloat16* __restrict__ Ahi, const __nv_bfloat16* __restrict__ Alo,
    const __nv_bfloat16* __restrict__ Bhi, const __nv_bfloat16* __restrict__ Blo,
    float* __restrict__ C, const float* __restrict__ b0)
{
    extern __shared__ char smem[];
    const uint32_t sbase = smem_u32(smem);

    const int tid  = threadIdx.x;
    const int lane = tid & 31;
    const int warp = tid >> 5;
    const int wm   = (warp & 1) * 32;
    const int wn   = (warp >> 1) * 16;
    const int m0 = blockIdx.y * 64;
    const int n0 = blockIdx.x * 64;

    uint32_t aOff[2];
    #pragma unroll
    for (int mf = 0; mf < 2; ++mf)
        aOff[mf] = (uint32_t)(((wm + mf * 16 + (lane & 15)) * LDT + (lane >> 4) * 8) * 2);
    const uint32_t bOff = (uint32_t)(((wn + (lane >> 4) * 8 + (lane & 7)) * LDT
                                      + ((lane >> 3) & 1) * 8) * 2);

    float acc[2][2][4];
    #pragma unroll
    for (int mf = 0; mf < 2; ++mf)
        #pragma unroll
        for (int nf = 0; nf < 2; ++nf)
            #pragma unroll
            for (int j = 0; j < 4; ++j) acc[mf][nf][j] = 0.f;

    auto prefetch = [&](int kc, int stg) {
        const int kb = kc * 64;
        const uint32_t s0 = sbase + stg * OSTG;
        #pragma unroll
        for (int i = 0; i < 2; ++i) {
            int c = tid + 256 * i;
            int r = c >> 3, k8 = (c & 7) * 8;
            uint32_t so = (r * LDT + k8) * 2;
            cp16(s0 + 0 * OARR + so, &Ahi[(m0 + r) * EDIM + kb + k8]);
            cp16(s0 + 1 * OARR + so, &Alo[(m0 + r) * EDIM + kb + k8]);
            cp16(s0 + 2 * OARR + so, &Bhi[(n0 + r) * EDIM + kb + k8]);
            cp16(s0 + 3 * OARR + so, &Blo[(n0 + r) * EDIM + kb + k8]);
        }
        CP_COMMIT();
    };

    prefetch(0, 0);

    for (int kc = 0; kc < 4; ++kc) {
        if (kc < 3) prefetch(kc + 1, (kc + 1) & 1);
        if (kc < 3) CP_WAIT1(); else CP_WAIT0();
        __syncthreads();

        const uint32_t s0 = sbase + (kc & 1) * OSTG;
        #pragma unroll
        for (int ks = 0; ks < 4; ++ks) {
            const uint32_t kByte = ks * 32;
            uint32_t ah[2][4], al[2][4], bh[4], bl[4];
            #pragma unroll
            for (int mf = 0; mf < 2; ++mf) {
                ldsm_x4(ah[mf], s0 + 0 * OARR + aOff[mf] + kByte);
                ldsm_x4(al[mf], s0 + 1 * OARR + aOff[mf] + kByte);
            }
            ldsm_x4(bh, s0 + 2 * OARR + bOff + kByte);
            ldsm_x4(bl, s0 + 3 * OARR + bOff + kByte);
            #pragma unroll
            for (int mf = 0; mf < 2; ++mf) {
                #pragma unroll
                for (int nf = 0; nf < 2; ++nf) {
                    mma16816(acc[mf][nf], ah[mf], bh[nf * 2], bh[nf * 2 + 1]);
                    mma16816(acc[mf][nf], ah[mf], bl[nf * 2], bl[nf * 2 + 1]);
                    mma16816(acc[mf][nf], al[mf], bh[nf * 2], bh[nf * 2 + 1]);
                }
            }
        }
        __syncthreads();
    }

    const int l4 = lane >> 2;
    const int l2 = (lane & 3) * 2;
    #pragma unroll
    for (int mf = 0; mf < 2; ++mf) {
        #pragma unroll
        for (int nf = 0; nf < 2; ++nf) {
            int gr = m0 + wm + mf * 16 + l4;
            int gc = n0 + wn + nf * 8 + l2;
            float r[4];
            #pragma unroll
            for (int j = 0; j < 4; ++j)
                r[j] = __logf(acc[mf][nf][j]) + b0[gc + (j & 1)];
            *(float2*)&C[gr * EDIM + gc]       = make_float2(r[0], r[1]);
            *(float2*)&C[(gr + 8) * EDIM + gc] = make_float2(r[2], r[3]);
        }
    }
}

// ---------------------------------------------------------------------------
extern "C" void kernel_launch(void* const* d_in, const int* in_sizes, int n_in,
                              void* d_out, int out_size)
{
    const float* x  = (const float*)d_in[0];
    const float* Wq = (const float*)d_in[1];
    const float* bq = (const float*)d_in[2];
    const float* Wk = (const float*)d_in[3];
    const float* bk = (const float*)d_in[4];
    const float* Wv = (const float*)d_in[5];
    const float* bv = (const float*)d_in[6];
    const float* Wo = (const float*)d_in[7];
    const float* bo = (const float*)d_in[8];
    float* out = (float*)d_out;

    static cudaStream_t s2;
    static cudaEvent_t evFork, evJoin;
    static bool init = false;
    if (!init) {
        cudaFuncSetAttribute(k_qkv_attn, cudaFuncAttributeMaxDynamicSharedMemorySize, FUSED_SMEM);
        cudaFuncSetAttribute(k_ogemm,    cudaFuncAttributeMaxDynamicSharedMemorySize, OSM);
        cudaStreamCreateWithFlags(&s2, cudaStreamNonBlocking);
        cudaEventCreateWithFlags(&evFork, cudaEventDisableTiming);
        cudaEventCreateWithFlags(&evJoin, cudaEventDisableTiming);
        init = true;
    }

    __nv_bfloat16 *Bhi, *Blo, *Chi, *Clo, *EOhi, *EOlo;
    cudaGetSymbolAddress((void**)&Bhi, g_Bhi);
    cudaGetSymbolAddress((void**)&Blo, g_Blo);
    cudaGetSymbolAddress((void**)&Chi, g_Chi);
    cudaGetSymbolAddress((void**)&Clo, g_Clo);
    cudaGetSymbolAddress((void**)&EOhi, g_EOhi);
    cudaGetSymbolAddress((void**)&EOlo, g_EOlo);

    // Fork: side stream converts Wo concurrently with the qkv path.
    cudaEventRecord(evFork, 0);
    cudaStreamWaitEvent(s2, evFork, 0);
    k_prep_o<<<64, 256, 0, s2>>>(Wo);                // 16384 quads

    // Main stream: Wqkv conversion -> fused attention.
    k_prep_qkv<<<192, 256>>>(Wq, Wk, Wv);            // 49152 quads
    {
        dim3 grid(NH, 32);
        k_qkv_attn<<<grid, 256, FUSED_SMEM>>>(x, Bhi, Blo, bq, bk, bv);
    }

    // Join, then output projection.
    cudaEventRecord(evJoin, s2);
    cudaStreamWaitEvent(0, evJoin, 0);
    {
        dim3 grid(EDIM / 64, NROWS / 64);  // (4, 32)
        k_ogemm<<<grid, 256, OSM>>>(EOhi, EOlo, Chi, Clo, out, bo);
    }
}

// round 13
// speedup vs baseline: 1.1686x; 1.1686x over previous
#include <cuda_runtime.h>
#include <cuda_bf16.h>
#include <cstdint>
#include <math.h>

// Problem constants: B=32, S=64, E=256, H=4, D=64
#define NROWS 2048
#define EDIM  256
#define NQKV  768
#define NH    4
#define NCTA  128

// ---------------- scratch (__device__ globals, no allocs) -------------------
__device__ __nv_bfloat16 g_Bhi[NQKV * EDIM],  g_Blo[NQKV * EDIM];    // exp(Wqkv) [n][k]
__device__ __nv_bfloat16 g_Chi[EDIM * EDIM],  g_Clo[EDIM * EDIM];    // exp(Wo)   [n][k]
__device__ __nv_bfloat16 g_EOhi[NROWS * EDIM], g_EOlo[NROWS * EDIM]; // exp(attn out)
__device__ unsigned g_barctr = 0;   // monotonic grid-barrier counter (never reset)

// ---------------- helpers (base ISA only — sm_103 non-variant) --------------
__device__ __forceinline__ uint32_t smem_u32(const void* p) {
    uint32_t a;
    asm("{ .reg .u64 t; cvta.to.shared.u64 t, %1; cvt.u32.u64 %0, t; }"
        : "=r"(a) : "l"(p));
    return a;
}
__device__ __forceinline__ void ldsm_x4(uint32_t* r, uint32_t addr) {
    asm volatile("ldmatrix.sync.aligned.m8n8.x4.shared.b16 {%0,%1,%2,%3}, [%4];"
                 : "=r"(r[0]), "=r"(r[1]), "=r"(r[2]), "=r"(r[3]) : "r"(addr));
}
__device__ __forceinline__ void mma16816(float* d, const uint32_t* a,
                                         uint32_t b0, uint32_t b1) {
    asm volatile(
        "mma.sync.aligned.m16n8k16.row.col.f32.bf16.bf16.f32 "
        "{%0,%1,%2,%3}, {%4,%5,%6,%7}, {%8,%9}, {%0,%1,%2,%3};"
        : "+f"(d[0]), "+f"(d[1]), "+f"(d[2]), "+f"(d[3])
        : "r"(a[0]), "r"(a[1]), "r"(a[2]), "r"(a[3]), "r"(b0), "r"(b1));
}
__device__ __forceinline__ void cp16(uint32_t s, const void* g) {
    asm volatile("cp.async.cg.shared.global [%0], [%1], 16;" :: "r"(s), "l"(g));
}
#define CP_COMMIT() asm volatile("cp.async.commit_group;" ::: "memory")
#define CP_WAIT1()  asm volatile("cp.async.wait_group 1;" ::: "memory")
#define CP_WAIT0()  asm volatile("cp.async.wait_group 0;" ::: "memory")

// exp + hi/lo split of 4 floats -> packed bf16x4 (uint2 each)
__device__ __forceinline__ void exp_split4(const float4& v, uint2& hi, uint2& lo) {
    float e[4] = {__expf(v.x), __expf(v.y), __expf(v.z), __expf(v.w)};
    __nv_bfloat16 h[4], l[4];
    #pragma unroll
    for (int j = 0; j < 4; ++j) {
        h[j] = __float2bfloat16(e[j]);
        l[j] = __float2bfloat16(e[j] - __bfloat162float(h[j]));
    }
    __nv_bfloat162 h0 = __halves2bfloat162(h[0], h[1]);
    __nv_bfloat162 h1 = __halves2bfloat162(h[2], h[3]);
    __nv_bfloat162 l0 = __halves2bfloat162(l[0], l[1]);
    __nv_bfloat162 l1 = __halves2bfloat162(l[2], l[3]);
    hi.x = *(uint32_t*)&h0; hi.y = *(uint32_t*)&h1;
    lo.x = *(uint32_t*)&l0; lo.y = *(uint32_t*)&l1;
}

// Grid barrier: monotonic-counter generation scheme — replay-safe, no reset.
// Valid because all 128 CTAs are co-resident (1 CTA/SM by smem, 128 < 148 SMs).
__device__ __forceinline__ void grid_barrier() {
    __syncthreads();
    if (threadIdx.x == 0) {
        __threadfence();
        unsigned v = atomicAdd(&g_barctr, 1);
        unsigned target = v - (v % NCTA) + NCTA;
        while ((int)(*(volatile unsigned*)&g_barctr - target) < 0)
            __nanosleep(64);
    }
    __syncthreads();
}

// ---------------------------------------------------------------------------
// smem layout (phase 1: fused qkv+attn; phase 2 reuses the front for ogemm)
// ---------------------------------------------------------------------------
#define LDTA 264                           // A row stride (bf16 elems)
#define A_ARR (64 * LDTA * 2)              // 33792 B
#define LDT 72                             // B row stride
#define B_ARR (64 * LDT * 2)               // 9216 B
#define OFF_A0 0
#define OFF_A1 A_ARR
#define OFF_B  (2 * A_ARR)                 // 67584
#define OFF_P  (OFF_B + 6 * B_ARR)         // 122880
#define OFF_V  (OFF_P + 64 * 65 * 4)       // 139520
#define OFF_INV (OFF_V + 64 * 68 * 4)      // 156928
#define FUSED_SMEM (OFF_INV + 256)         // 157184
// phase-2 (ogemm) layout: 2-stage double buffer at smem base
#define OARR (64 * LDT * 2)                // 9216
#define OSTG (4 * OARR)                    // 36864

// ---------------------------------------------------------------------------
// ONE persistent kernel: weight conversion -> barrier -> qkv+attn -> barrier
// -> output projection. CTA = (h, b), grid (4, 32) = 128 CTAs.
// ---------------------------------------------------------------------------
__global__ void __launch_bounds__(256) k_fused(
    const float* __restrict__ x,
    const float* __restrict__ Wq, const float* __restrict__ Wk,
    const float* __restrict__ Wv, const float* __restrict__ Wo,
    const float* __restrict__ bq, const float* __restrict__ bk,
    const float* __restrict__ bv, const float* __restrict__ bo,
    float* __restrict__ out)
{
    extern __shared__ char smem[];
    const uint32_t sbase = smem_u32(smem);

    const int tid  = threadIdx.x;
    const int lane = tid & 31;
    const int warp = tid >> 5;
    const int wm   = (warp & 1) * 32;
    const int wn   = (warp >> 1) * 16;
    const int h = blockIdx.x;
    const int b = blockIdx.y;
    const int bid = b * NH + h;

    // ======================= PHASE 0: weight conversion ====================
    // 262144 elems = 65536 quads; 128 CTAs x 256 thr x 2 quads.
    #pragma unroll
    for (int i = 0; i < 2; ++i) {
        int q = bid * 512 + i * 256 + tid;
        uint2 h2, l2;
        if (q < (NQKV * EDIM) / 4) {
            int idx = q * 4;
            int n = idx / EDIM, k = idx - n * EDIM;
            const float* W = (n < 256) ? Wq : ((n < 512) ? Wk : Wv);
            exp_split4(*(const float4*)&W[(n & 255) * EDIM + k], h2, l2);
            *(uint2*)&g_Bhi[idx] = h2;
            *(uint2*)&g_Blo[idx] = l2;
        } else {
            int idx = q * 4 - NQKV * EDIM;
            exp_split4(*(const float4*)&Wo[idx], h2, l2);
            *(uint2*)&g_Chi[idx] = h2;
            *(uint2*)&g_Clo[idx] = l2;
        }
    }
    grid_barrier();

    // ======================= PHASE 1: qkv GEMM + attention =================
    {
        float* P   = (float*)(smem + OFF_P);   // [64][65]
        float* V   = (float*)(smem + OFF_V);   // [64][68]
        float* inv = (float*)(smem + OFF_INV);
        const int m0 = b * 64;

        auto prefB = [&](int it) {
            const int reg = it >> 2, kc = it & 3;
            const int brow0 = reg * 256 + h * 64;
            const uint32_t s0 = sbase + OFF_B + (uint32_t)(it % 3) * (2 * B_ARR);
            #pragma unroll
            for (int i = 0; i < 2; ++i) {
                int c = tid + 256 * i;
                int r = c >> 3, k8 = (c & 7) * 8;
                uint32_t so = (r * LDT + k8) * 2;
                cp16(s0 + so,         &g_Bhi[(brow0 + r) * EDIM + kc * 64 + k8]);
                cp16(s0 + B_ARR + so, &g_Blo[(brow0 + r) * EDIM + kc * 64 + k8]);
            }
            CP_COMMIT();
        };
        prefB(0); prefB(1);

        // prolog: LDG x fp32, exp+split, STS into A hi/lo tiles
        #pragma unroll
        for (int i = 0; i < 8; ++i) {
            int c = tid + 256 * i;
            int r = c >> 5, k8 = (c & 31) * 8;
            const float4* xs = (const float4*)&x[(m0 + r) * EDIM + k8];
            float4 v0 = xs[0], v1 = xs[1];
            uint2 h0, l0, h1, l1;
            exp_split4(v0, h0, l0);
            exp_split4(v1, h1, l1);
            uint32_t so = (r * LDTA + k8) * 2;
            *(uint4*)(smem + OFF_A0 + so) = make_uint4(h0.x, h0.y, h1.x, h1.y);
            *(uint4*)(smem + OFF_A1 + so) = make_uint4(l0.x, l0.y, l1.x, l1.y);
        }

        uint32_t aOff[2];
        #pragma unroll
        for (int mf = 0; mf < 2; ++mf)
            aOff[mf] = (uint32_t)(((wm + mf * 16 + (lane & 15)) * LDTA + (lane >> 4) * 8) * 2);
        const uint32_t bOff = (uint32_t)(((wn + (lane >> 4) * 8 + (lane & 7)) * LDT
                                          + ((lane >> 3) & 1) * 8) * 2);

        float acc[2][2][4];
        #pragma unroll
        for (int mf = 0; mf < 2; ++mf)
            #pragma unroll
            for (int nf = 0; nf < 2; ++nf)
                #pragma unroll
                for (int j = 0; j < 4; ++j) acc[mf][nf][j] = 0.f;

        for (int it = 0; it < 12; ++it) {
            if (it < 11) CP_WAIT1(); else CP_WAIT0();
            __syncthreads();
            if (it < 10) prefB(it + 2);

            const int kc = it & 3;
            const uint32_t sB = sbase + OFF_B + (uint32_t)(it % 3) * (2 * B_ARR);
            #pragma unroll
            for (int ks = 0; ks < 4; ++ks) {
                const uint32_t aByte = (uint32_t)((kc * 64 + ks * 16) * 2);
                const uint32_t kByte = ks * 32;
                uint32_t ah[2][4], al[2][4], bh[4], bl[4];
                #pragma unroll
                for (int mf = 0; mf < 2; ++mf) {
                    ldsm_x4(ah[mf], sbase + OFF_A0 + aOff[mf] + aByte);
                    ldsm_x4(al[mf], sbase + OFF_A1 + aOff[mf] + aByte);
                }
                ldsm_x4(bh, sB + bOff + kByte);
                ldsm_x4(bl, sB + B_ARR + bOff + kByte);
                #pragma unroll
                for (int mf = 0; mf < 2; ++mf) {
                    #pragma unroll
                    for (int nf = 0; nf < 2; ++nf) {
                        mma16816(acc[mf][nf], ah[mf], bh[nf * 2], bh[nf * 2 + 1]);
                        mma16816(acc[mf][nf], ah[mf], bl[nf * 2], bl[nf * 2 + 1]);
                        mma16816(acc[mf][nf], al[mf], bh[nf * 2], bh[nf * 2 + 1]);
                    }
                }
            }

            if (kc == 3) {
                const int reg = it >> 2;
                #pragma unroll
                for (int mf = 0; mf < 2; ++mf)
                    #pragma unroll
                    for (int nf = 0; nf < 2; ++nf)
                        #pragma unroll
                        for (int j = 0; j < 4; ++j) {
                            int s = wm + mf * 16 + (lane >> 2) + (j >> 1) * 8;
                            int d = wn + nf * 8 + (lane & 3) * 2 + (j & 1);
                            float v = acc[mf][nf][j];
                            if (reg == 0)      P[s * 65 + d]  = v * __expf(bq[h * 64 + d]);
                            else if (reg == 1) P[s * 65 + d] *= v * __expf(bk[h * 64 + d]);
                            else               V[s * 68 + d]  = __logf(v) + bv[h * 64 + d];
                            acc[mf][nf][j] = 0.f;
                        }
            }
        }
        __syncthreads();

        if (tid < 64) {
            float s = 0.f;
            #pragma unroll
            for (int j = 0; j < 64; ++j) s += P[tid * 65 + j];
            inv[tid] = 1.0f / s;
        }
        __syncthreads();

        const int tx = tid & 15;
        const int ty = tid >> 4;
        float oacc[4][4] = {};
        #pragma unroll 4
        for (int d = 0; d < 64; ++d) {
            float p0 = P[(4 * ty + 0) * 65 + d];
            float p1 = P[(4 * ty + 1) * 65 + d];
            float p2 = P[(4 * ty + 2) * 65 + d];
            float p3 = P[(4 * ty + 3) * 65 + d];
            float4 v4 = *(const float4*)&V[d * 68 + 4 * tx];
            oacc[0][0] += p0 * v4.x; oacc[0][1] += p0 * v4.y;
            oacc[0][2] += p0 * v4.z; oacc[0][3] += p0 * v4.w;
            oacc[1][0] += p1 * v4.x; oacc[1][1] += p1 * v4.y;
            oacc[1][2] += p1 * v4.z; oacc[1][3] += p1 * v4.w;
            oacc[2][0] += p2 * v4.x; oacc[2][1] += p2 * v4.y;
            oacc[2][2] += p2 * v4.z; oacc[2][3] += p2 * v4.w;
            oacc[3][0] += p3 * v4.x; oacc[3][1] += p3 * v4.y;
            oacc[3][2] += p3 * v4.z; oacc[3][3] += p3 * v4.w;
        }
        #pragma unroll
        for (int r = 0; r < 4; ++r) {
            float iv = inv[4 * ty + r];
            int grow = b * 64 + 4 * ty + r;
            #pragma unroll
            for (int c = 0; c < 4; ++c) {
                float eo = __expf(oacc[r][c] * iv);
                __nv_bfloat16 hb = __float2bfloat16(eo);
                int gi = grow * EDIM + h * 64 + 4 * tx + c;
                g_EOhi[gi] = hb;
                g_EOlo[gi] = __float2bfloat16(eo - __bfloat162float(hb));
            }
        }
    }
    grid_barrier();

    // ======================= PHASE 2: output projection ====================
    {
        const int m0 = b * 64;         // row tile
        const int n0 = h * 64;         // col tile (EDIM/64 = 4 = NH)

        uint32_t aOff[2];
        #pragma unroll
        for (int mf = 0; mf < 2; ++mf)
            aOff[mf] = (uint32_t)(((wm + mf * 16 + (lane & 15)) * LDT + (lane >> 4) * 8) * 2);
        const uint32_t bOff = (uint32_t)(((wn + (lane >> 4) * 8 + (lane & 7)) * LDT
                                          + ((lane >> 3) & 1) * 8) * 2);

        float acc[2][2][4];
        #pragma unroll
        for (int mf = 0; mf < 2; ++mf)
            #pragma unroll
            for (int nf = 0; nf < 2; ++nf)
                #pragma unroll
                for (int j = 0; j < 4; ++j) acc[mf][nf][j] = 0.f;

        auto prefetch = [&](int kc, int stg) {
            const int kb = kc * 64;
            const uint32_t s0 = sbase + stg * OSTG;
            #pragma unroll
            for (int i = 0; i < 2; ++i) {
                int c = tid + 256 * i;
                int r = c >> 3, k8 = (c & 7) * 8;
                uint32_t so = (r * LDT + k8) * 2;
                cp16(s0 + 0 * OARR + so, &g_EOhi[(m0 + r) * EDIM + kb + k8]);
                cp16(s0 + 1 * OARR + so, &g_EOlo[(m0 + r) * EDIM + kb + k8]);
                cp16(s0 + 2 * OARR + so, &g_Chi[(n0 + r) * EDIM + kb + k8]);
                cp16(s0 + 3 * OARR + so, &g_Clo[(n0 + r) * EDIM + kb + k8]);
            }
            CP_COMMIT();
        };

        prefetch(0, 0);

        for (int kc = 0; kc < 4; ++kc) {
            if (kc < 3) prefetch(kc + 1, (kc + 1) & 1);
            if (kc < 3) CP_WAIT1(); else CP_WAIT0();
            __syncthreads();

            const uint32_t s0 = sbase + (kc & 1) * OSTG;
            #pragma unroll
            for (int ks = 0; ks < 4; ++ks) {
                const uint32_t kByte = ks * 32;
                uint32_t ah[2][4], al[2][4], bh[4], bl[4];
                #pragma unroll
                for (int mf = 0; mf < 2; ++mf) {
                    ldsm_x4(ah[mf], s0 + 0 * OARR + aOff[mf] + kByte);
                    ldsm_x4(al[mf], s0 + 1 * OARR + aOff[mf] + kByte);
                }
                ldsm_x4(bh, s0 + 2 * OARR + bOff + kByte);
                ldsm_x4(bl, s0 + 3 * OARR + bOff + kByte);
                #pragma unroll
                for (int mf = 0; mf < 2; ++mf) {
                    #pragma unroll
                    for (int nf = 0; nf < 2; ++nf) {
                        mma16816(acc[mf][nf], ah[mf], bh[nf * 2], bh[nf * 2 + 1]);
                        mma16816(acc[mf][nf], ah[mf], bl[nf * 2], bl[nf * 2 + 1]);
                        mma16816(acc[mf][nf], al[mf], bh[nf * 2], bh[nf * 2 + 1]);
                    }
                }
            }
            __syncthreads();
        }

        const int l4 = lane >> 2;
        const int l2 = (lane & 3) * 2;
        #pragma unroll
        for (int mf = 0; mf < 2; ++mf) {
            #pragma unroll
            for (int nf = 0; nf < 2; ++nf) {
                int gr = m0 + wm + mf * 16 + l4;
                int gc = n0 + wn + nf * 8 + l2;
                float r[4];
                #pragma unroll
                for (int j = 0; j < 4; ++j)
                    r[j] = __logf(acc[mf][nf][j]) + bo[gc + (j & 1)];
                *(float2*)&out[gr * EDIM + gc]       = make_float2(r[0], r[1]);
                *(float2*)&out[(gr + 8) * EDIM + gc] = make_float2(r[2], r[3]);
            }
        }
    }
}

// ---------------------------------------------------------------------------
extern "C" void kernel_launch(void* const* d_in, const int* in_sizes, int n_in,
                              void* d_out, int out_size)
{
    const float* x  = (const float*)d_in[0];
    const float* Wq = (const float*)d_in[1];
    const float* bq = (const float*)d_in[2];
    const float* Wk = (const float*)d_in[3];
    const float* bk = (const float*)d_in[4];
    const float* Wv = (const float*)d_in[5];
    const float* bv = (const float*)d_in[6];
    const float* Wo = (const float*)d_in[7];
    const float* bo = (const float*)d_in[8];
    float* out = (float*)d_out;

    static bool init = false;
    if (!init) {
        cudaFuncSetAttribute(k_fused, cudaFuncAttributeMaxDynamicSharedMemorySize, FUSED_SMEM);
        init = true;
    }

    dim3 grid(NH, 32);   // 128 CTAs — all co-resident (1/SM, 148 SMs)
    k_fused<<<grid, 256, FUSED_SMEM>>>(x, Wq, Wk, Wv, Wo, bq, bk, bv, bo, out);
}

// round 14
// speedup vs baseline: 1.2528x; 1.0721x over previous
#include <cuda_runtime.h>
#include <cuda_bf16.h>
#include <cstdint>
#include <math.h>

// Problem constants: B=32, S=64, E=256, H=4, D=64
#define NROWS 2048
#define EDIM  256
#define NQKV  768
#define NH    4
#define NCTA  128

// ---------------- scratch (__device__ globals, no allocs) -------------------
__device__ __nv_bfloat16 g_Bhi[NQKV * EDIM],  g_Blo[NQKV * EDIM];    // exp(Wqkv) [n][k]
__device__ __nv_bfloat16 g_Chi[EDIM * EDIM],  g_Clo[EDIM * EDIM];    // exp(Wo)   [n][k]
__device__ __nv_bfloat16 g_EOhi[NROWS * EDIM], g_EOlo[NROWS * EDIM]; // exp(attn out)
__device__ unsigned g_barctr = 0;   // monotonic grid-barrier counter (never reset)

// ---------------- helpers (base ISA only — sm_103 non-variant) --------------
__device__ __forceinline__ uint32_t smem_u32(const void* p) {
    uint32_t a;
    asm("{ .reg .u64 t; cvta.to.shared.u64 t, %1; cvt.u32.u64 %0, t; }"
        : "=r"(a) : "l"(p));
    return a;
}
__device__ __forceinline__ void ldsm_x4(uint32_t* r, uint32_t addr) {
    asm volatile("ldmatrix.sync.aligned.m8n8.x4.shared.b16 {%0,%1,%2,%3}, [%4];"
                 : "=r"(r[0]), "=r"(r[1]), "=r"(r[2]), "=r"(r[3]) : "r"(addr));
}
__device__ __forceinline__ void mma16816(float* d, const uint32_t* a,
                                         uint32_t b0, uint32_t b1) {
    asm volatile(
        "mma.sync.aligned.m16n8k16.row.col.f32.bf16.bf16.f32 "
        "{%0,%1,%2,%3}, {%4,%5,%6,%7}, {%8,%9}, {%0,%1,%2,%3};"
        : "+f"(d[0]), "+f"(d[1]), "+f"(d[2]), "+f"(d[3])
        : "r"(a[0]), "r"(a[1]), "r"(a[2]), "r"(a[3]), "r"(b0), "r"(b1));
}
__device__ __forceinline__ void cp16(uint32_t s, const void* g) {
    asm volatile("cp.async.cg.shared.global [%0], [%1], 16;" :: "r"(s), "l"(g));
}
#define CP_COMMIT() asm volatile("cp.async.commit_group;" ::: "memory")
#define CP_WAIT1()  asm volatile("cp.async.wait_group 1;" ::: "memory")
#define CP_WAIT0()  asm volatile("cp.async.wait_group 0;" ::: "memory")

// hi/lo split of 4 floats -> packed bf16x4 (uint2 each); optional exp first
__device__ __forceinline__ void split4(const float4& v, uint2& hi, uint2& lo) {
    float e[4] = {v.x, v.y, v.z, v.w};
    __nv_bfloat16 h[4], l[4];
    #pragma unroll
    for (int j = 0; j < 4; ++j) {
        h[j] = __float2bfloat16(e[j]);
        l[j] = __float2bfloat16(e[j] - __bfloat162float(h[j]));
    }
    __nv_bfloat162 h0 = __halves2bfloat162(h[0], h[1]);
    __nv_bfloat162 h1 = __halves2bfloat162(h[2], h[3]);
    __nv_bfloat162 l0 = __halves2bfloat162(l[0], l[1]);
    __nv_bfloat162 l1 = __halves2bfloat162(l[2], l[3]);
    hi.x = *(uint32_t*)&h0; hi.y = *(uint32_t*)&h1;
    lo.x = *(uint32_t*)&l0; lo.y = *(uint32_t*)&l1;
}
__device__ __forceinline__ void exp_split4(const float4& v, uint2& hi, uint2& lo) {
    float4 e = make_float4(__expf(v.x), __expf(v.y), __expf(v.z), __expf(v.w));
    split4(e, hi, lo);
}

// Grid barrier: monotonic-counter generation scheme — replay-safe, no reset.
__device__ __forceinline__ void grid_barrier() {
    __syncthreads();
    if (threadIdx.x == 0) {
        __threadfence();
        unsigned v = atomicAdd(&g_barctr, 1);
        unsigned target = v - (v % NCTA) + NCTA;
        while ((int)(*(volatile unsigned*)&g_barctr - target) < 0)
            __nanosleep(64);
    }
    __syncthreads();
}

// ---------------------------------------------------------------------------
// smem layout
// ---------------------------------------------------------------------------
#define LDTA 264                           // A row stride (bf16 elems)
#define A_ARR (64 * LDTA * 2)              // 33792 B
#define LDT 72                             // B / attn-tile row stride
#define B_ARR (64 * LDT * 2)               // 9216 B
#define OFF_A0 0
#define OFF_A1 A_ARR
#define OFF_B  (2 * A_ARR)                 // 67584 ; 3 stages x (hi,lo)
#define OFF_P  (OFF_B + 6 * B_ARR)         // 122880 ; P fp32 [64][68]
#define OFF_INV (OFF_P + 64 * 68 * 4)      // 140288 ; inv[64]
#define OFF_BIAS (OFF_INV + 256)           // 140544 ; exp(bq),exp(bk),bv [192]
#define FUSED_SMEM (OFF_BIAS + 768)        // 141312
// phase-1 tail: split tiles reuse dead B stages
//   Vt hi = OFF_B, Vt lo = OFF_B+B_ARR, P hi = OFF_B+2*B_ARR, P lo = +3*B_ARR
// phase-2 (ogemm): 2-stage double buffer at smem base
#define OARR (64 * LDT * 2)                // 9216
#define OSTG (4 * OARR)                    // 36864

// ---------------------------------------------------------------------------
// ONE persistent kernel. CTA = (h, b), grid (4, 32) = 128 CTAs (all resident).
// ---------------------------------------------------------------------------
__global__ void __launch_bounds__(256) k_fused(
    const float* __restrict__ x,
    const float* __restrict__ Wq, const float* __restrict__ Wk,
    const float* __restrict__ Wv, const float* __restrict__ Wo,
    const float* __restrict__ bq, const float* __restrict__ bk,
    const float* __restrict__ bv, const float* __restrict__ bo,
    float* __restrict__ out)
{
    extern __shared__ char smem[];
    const uint32_t sbase = smem_u32(smem);

    const int tid  = threadIdx.x;
    const int lane = tid & 31;
    const int warp = tid >> 5;
    const int wm   = (warp & 1) * 32;
    const int wn   = (warp >> 1) * 16;
    const int h = blockIdx.x;
    const int b = blockIdx.y;
    const int bid = b * NH + h;

    // ======================= PHASE 0: weight conversion ====================
    #pragma unroll
    for (int i = 0; i < 2; ++i) {
        int q = bid * 512 + i * 256 + tid;
        uint2 h2, l2;
        if (q < (NQKV * EDIM) / 4) {
            int idx = q * 4;
            int n = idx / EDIM, k = idx - n * EDIM;
            const float* W = (n < 256) ? Wq : ((n < 512) ? Wk : Wv);
            exp_split4(*(const float4*)&W[(n & 255) * EDIM + k], h2, l2);
            *(uint2*)&g_Bhi[idx] = h2;
            *(uint2*)&g_Blo[idx] = l2;
        } else {
            int idx = q * 4 - NQKV * EDIM;
            exp_split4(*(const float4*)&Wo[idx], h2, l2);
            *(uint2*)&g_Chi[idx] = h2;
            *(uint2*)&g_Clo[idx] = l2;
        }
    }
    grid_barrier();

    // ======================= PHASE 1: qkv GEMM + attention =================
    {
        float* P    = (float*)(smem + OFF_P);     // [64][68] fp32
        float* inv  = (float*)(smem + OFF_INV);
        float* sBias = (float*)(smem + OFF_BIAS); // [0:64)=exp(bq) [64:128)=exp(bk) [128:192)=bv
        const int m0 = b * 64;

        auto prefB = [&](int it) {
            const int reg = it >> 2, kc = it & 3;
            const int brow0 = reg * 256 + h * 64;
            const uint32_t s0 = sbase + OFF_B + (uint32_t)(it % 3) * (2 * B_ARR);
            #pragma unroll
            for (int i = 0; i < 2; ++i) {
                int c = tid + 256 * i;
                int r = c >> 3, k8 = (c & 7) * 8;
                uint32_t so = (r * LDT + k8) * 2;
                cp16(s0 + so,         &g_Bhi[(brow0 + r) * EDIM + kc * 64 + k8]);
                cp16(s0 + B_ARR + so, &g_Blo[(brow0 + r) * EDIM + kc * 64 + k8]);
            }
            CP_COMMIT();
        };
        prefB(0); prefB(1);

        // bias preload
        if (tid < 192) {
            int reg = tid >> 6, d = tid & 63;
            float v = (reg == 0) ? __expf(bq[h * 64 + d])
                    : (reg == 1) ? __expf(bk[h * 64 + d])
                                 : bv[h * 64 + d];
            sBias[tid] = v;
        }

        // prolog: LDG x fp32, exp+split, STS into A hi/lo tiles
        #pragma unroll
        for (int i = 0; i < 8; ++i) {
            int c = tid + 256 * i;
            int r = c >> 5, k8 = (c & 31) * 8;
            const float4* xs = (const float4*)&x[(m0 + r) * EDIM + k8];
            float4 v0 = xs[0], v1 = xs[1];
            uint2 h0, l0, h1, l1;
            exp_split4(v0, h0, l0);
            exp_split4(v1, h1, l1);
            uint32_t so = (r * LDTA + k8) * 2;
            *(uint4*)(smem + OFF_A0 + so) = make_uint4(h0.x, h0.y, h1.x, h1.y);
            *(uint4*)(smem + OFF_A1 + so) = make_uint4(l0.x, l0.y, l1.x, l1.y);
        }

        uint32_t aOff[2];
        #pragma unroll
        for (int mf = 0; mf < 2; ++mf)
            aOff[mf] = (uint32_t)(((wm + mf * 16 + (lane & 15)) * LDTA + (lane >> 4) * 8) * 2);
        const uint32_t bOff = (uint32_t)(((wn + (lane >> 4) * 8 + (lane & 7)) * LDT
                                          + ((lane >> 3) & 1) * 8) * 2);

        float acc[2][2][4];
        #pragma unroll
        for (int mf = 0; mf < 2; ++mf)
            #pragma unroll
            for (int nf = 0; nf < 2; ++nf)
                #pragma unroll
                for (int j = 0; j < 4; ++j) acc[mf][nf][j] = 0.f;

        __nv_bfloat16* sVh = (__nv_bfloat16*)(smem + OFF_B);
        __nv_bfloat16* sVl = (__nv_bfloat16*)(smem + OFF_B + B_ARR);

        for (int it = 0; it < 12; ++it) {
            if (it < 11) CP_WAIT1(); else CP_WAIT0();
            __syncthreads();
            if (it < 10) prefB(it + 2);

            const int kc = it & 3;
            const uint32_t sB = sbase + OFF_B + (uint32_t)(it % 3) * (2 * B_ARR);
            #pragma unroll
            for (int ks = 0; ks < 4; ++ks) {
                const uint32_t aByte = (uint32_t)((kc * 64 + ks * 16) * 2);
                const uint32_t kByte = ks * 32;
                uint32_t ah[2][4], al[2][4], bh[4], bl[4];
                #pragma unroll
                for (int mf = 0; mf < 2; ++mf) {
                    ldsm_x4(ah[mf], sbase + OFF_A0 + aOff[mf] + aByte);
                    ldsm_x4(al[mf], sbase + OFF_A1 + aOff[mf] + aByte);
                }
                ldsm_x4(bh, sB + bOff + kByte);
                ldsm_x4(bl, sB + B_ARR + bOff + kByte);
                #pragma unroll
                for (int mf = 0; mf < 2; ++mf) {
                    #pragma unroll
                    for (int nf = 0; nf < 2; ++nf) {
                        mma16816(acc[mf][nf], ah[mf], bh[nf * 2], bh[nf * 2 + 1]);
                        mma16816(acc[mf][nf], ah[mf], bl[nf * 2], bl[nf * 2 + 1]);
                        mma16816(acc[mf][nf], al[mf], bh[nf * 2], bh[nf * 2 + 1]);
                    }
                }
            }

            if (kc == 3) {
                const int reg = it >> 2;
                #pragma unroll
                for (int mf = 0; mf < 2; ++mf)
                    #pragma unroll
                    for (int nf = 0; nf < 2; ++nf)
                        #pragma unroll
                        for (int j = 0; j < 4; ++j) {
                            int s = wm + mf * 16 + (lane >> 2) + (j >> 1) * 8;
                            int d = wn + nf * 8 + (lane & 3) * 2 + (j & 1);
                            float v = acc[mf][nf][j];
                            if (reg == 0) {
                                P[s * 68 + d] = v * sBias[d];
                            } else if (reg == 1) {
                                P[s * 68 + d] *= v * sBias[64 + d];
                            } else {
                                // v-values, stored TRANSPOSED as bf16 hi/lo:
                                // Vt[feature d][token s] — B operand for P@V mma.
                                float vv = __logf(v) + sBias[128 + d];
                                __nv_bfloat16 hb = __float2bfloat16(vv);
                                sVh[d * LDT + s] = hb;
                                sVl[d * LDT + s] = __float2bfloat16(vv - __bfloat162float(hb));
                            }
                            acc[mf][nf][j] = 0.f;
                        }
            }
        }
        __syncthreads();   // P fp32 + Vt bf16 complete

        // ---- parallel rowsum -> inv (4 threads/row + shfl combine) --------
        {
            int r = tid >> 2, seg = tid & 3;
            const float* pr = &P[r * 68 + seg * 16];
            float s = 0.f;
            #pragma unroll
            for (int g = 0; g < 4; ++g) {
                float4 p4 = *(const float4*)&pr[g * 4];
                s += p4.x + p4.y + p4.z + p4.w;
            }
            s += __shfl_xor_sync(0xffffffffu, s, 1);
            s += __shfl_xor_sync(0xffffffffu, s, 2);
            if (seg == 0) inv[r] = 1.0f / s;
        }
        __syncthreads();

        // ---- attn = P * inv -> bf16 hi/lo split tiles ---------------------
        {
            __nv_bfloat16* sPh = (__nv_bfloat16*)(smem + OFF_B + 2 * B_ARR);
            __nv_bfloat16* sPl = (__nv_bfloat16*)(smem + OFF_B + 3 * B_ARR);
            int r = tid >> 2, c0 = (tid & 3) * 16;
            float iv = inv[r];
            #pragma unroll
            for (int g = 0; g < 4; ++g) {
                float4 p4 = *(const float4*)&P[r * 68 + c0 + g * 4];
                p4.x *= iv; p4.y *= iv; p4.z *= iv; p4.w *= iv;
                uint2 h2, l2; split4(p4, h2, l2);
                *(uint2*)&sPh[r * LDT + c0 + g * 4] = h2;
                *(uint2*)&sPl[r * LDT + c0 + g * 4] = l2;
            }
        }
        __syncthreads();

        // ---- out = attn @ V on tensor pipe; EO = exp(out) -----------------
        {
            const uint32_t PHB = sbase + OFF_B + 2 * B_ARR;
            const uint32_t PLB = sbase + OFF_B + 3 * B_ARR;
            const uint32_t VHB = sbase + OFF_B;
            const uint32_t VLB = sbase + OFF_B + B_ARR;
            uint32_t aO[2];
            #pragma unroll
            for (int mf = 0; mf < 2; ++mf)
                aO[mf] = (uint32_t)(((wm + mf * 16 + (lane & 15)) * LDT + (lane >> 4) * 8) * 2);

            #pragma unroll
            for (int ks = 0; ks < 4; ++ks) {
                const uint32_t kByte = ks * 32;
                uint32_t ah[2][4], al[2][4], bh[4], bl[4];
                #pragma unroll
                for (int mf = 0; mf < 2; ++mf) {
                    ldsm_x4(ah[mf], PHB + aO[mf] + kByte);
                    ldsm_x4(al[mf], PLB + aO[mf] + kByte);
                }
                ldsm_x4(bh, VHB + bOff + kByte);
                ldsm_x4(bl, VLB + bOff + kByte);
                #pragma unroll
                for (int mf = 0; mf < 2; ++mf) {
                    #pragma unroll
                    for (int nf = 0; nf < 2; ++nf) {
                        mma16816(acc[mf][nf], ah[mf], bh[nf * 2], bh[nf * 2 + 1]);
                        mma16816(acc[mf][nf], ah[mf], bl[nf * 2], bl[nf * 2 + 1]);
                        mma16816(acc[mf][nf], al[mf], bh[nf * 2], bh[nf * 2 + 1]);
                    }
                }
            }

            // epilogue: EO = exp(out), packed bf16x2 global stores
            #pragma unroll
            for (int mf = 0; mf < 2; ++mf)
                #pragma unroll
                for (int nf = 0; nf < 2; ++nf)
                    #pragma unroll
                    for (int jp = 0; jp < 2; ++jp) {
                        int s = wm + mf * 16 + (lane >> 2) + jp * 8;
                        int e = wn + nf * 8 + (lane & 3) * 2;
                        float eo0 = __expf(acc[mf][nf][jp * 2 + 0]);
                        float eo1 = __expf(acc[mf][nf][jp * 2 + 1]);
                        __nv_bfloat16 h0 = __float2bfloat16(eo0);
                        __nv_bfloat16 h1 = __float2bfloat16(eo1);
                        __nv_bfloat162 hh = __halves2bfloat162(h0, h1);
                        __nv_bfloat162 ll = __halves2bfloat162(
                            __float2bfloat16(eo0 - __bfloat162float(h0)),
                            __float2bfloat16(eo1 - __bfloat162float(h1)));
                        int gi = (b * 64 + s) * EDIM + h * 64 + e;
                        *(uint32_t*)&g_EOhi[gi] = *(uint32_t*)&hh;
                        *(uint32_t*)&g_EOlo[gi] = *(uint32_t*)&ll;
                    }
        }
    }
    grid_barrier();

    // ======================= PHASE 2: output projection ====================
    {
        const int m0 = b * 64;         // row tile
        const int n0 = h * 64;         // col tile (EDIM/64 = 4 = NH)

        uint32_t aOff[2];
        #pragma unroll
        for (int mf = 0; mf < 2; ++mf)
            aOff[mf] = (uint32_t)(((wm + mf * 16 + (lane & 15)) * LDT + (lane >> 4) * 8) * 2);
        const uint32_t bOff = (uint32_t)(((wn + (lane >> 4) * 8 + (lane & 7)) * LDT
                                          + ((lane >> 3) & 1) * 8) * 2);

        float acc[2][2][4];
        #pragma unroll
        for (int mf = 0; mf < 2; ++mf)
            #pragma unroll
            for (int nf = 0; nf < 2; ++nf)
                #pragma unroll
                for (int j = 0; j < 4; ++j) acc[mf][nf][j] = 0.f;

        auto prefetch = [&](int kc, int stg) {
            const int kb = kc * 64;
            const uint32_t s0 = sbase + stg * OSTG;
            #pragma unroll
            for (int i = 0; i < 2; ++i) {
                int c = tid + 256 * i;
                int r = c >> 3, k8 = (c & 7) * 8;
                uint32_t so = (r * LDT + k8) * 2;
                cp16(s0 + 0 * OARR + so, &g_EOhi[(m0 + r) * EDIM + kb + k8]);
                cp16(s0 + 1 * OARR + so, &g_EOlo[(m0 + r) * EDIM + kb + k8]);
                cp16(s0 + 2 * OARR + so, &g_Chi[(n0 + r) * EDIM + kb + k8]);
                cp16(s0 + 3 * OARR + so, &g_Clo[(n0 + r) * EDIM + kb + k8]);
            }
            CP_COMMIT();
        };

        prefetch(0, 0);

        for (int kc = 0; kc < 4; ++kc) {
            if (kc < 3) prefetch(kc + 1, (kc + 1) & 1);
            if (kc < 3) CP_WAIT1(); else CP_WAIT0();
            __syncthreads();

            const uint32_t s0 = sbase + (kc & 1) * OSTG;
            #pragma unroll
            for (int ks = 0; ks < 4; ++ks) {
                const uint32_t kByte = ks * 32;
                uint32_t ah[2][4], al[2][4], bh[4], bl[4];
                #pragma unroll
                for (int mf = 0; mf < 2; ++mf) {
                    ldsm_x4(ah[mf], s0 + 0 * OARR + aOff[mf] + kByte);
                    ldsm_x4(al[mf], s0 + 1 * OARR + aOff[mf] + kByte);
                }
                ldsm_x4(bh, s0 + 2 * OARR + bOff + kByte);
                ldsm_x4(bl, s0 + 3 * OARR + bOff + kByte);
                #pragma unroll
                for (int mf = 0; mf < 2; ++mf) {
                    #pragma unroll
                    for (int nf = 0; nf < 2; ++nf) {
                        mma16816(acc[mf][nf], ah[mf], bh[nf * 2], bh[nf * 2 + 1]);
                        mma16816(acc[mf][nf], ah[mf], bl[nf * 2], bl[nf * 2 + 1]);
                        mma16816(acc[mf][nf], al[mf], bh[nf * 2], bh[nf * 2 + 1]);
                    }
                }
            }
        }

        const int l4 = lane >> 2;
        const int l2 = (lane & 3) * 2;
        #pragma unroll
        for (int mf = 0; mf < 2; ++mf) {
            #pragma unroll
            for (int nf = 0; nf < 2; ++nf) {
                int gr = m0 + wm + mf * 16 + l4;
                int gc = n0 + wn + nf * 8 + l2;
                float r[4];
                #pragma unroll
                for (int j = 0; j < 4; ++j)
                    r[j] = __logf(acc[mf][nf][j]) + bo[gc + (j & 1)];
                *(float2*)&out[gr * EDIM + gc]       = make_float2(r[0], r[1]);
                *(float2*)&out[(gr + 8) * EDIM + gc] = make_float2(r[2], r[3]);
            }
        }
    }
}

// ---------------------------------------------------------------------------
extern "C" void kernel_launch(void* const* d_in, const int* in_sizes, int n_in,
                              void* d_out, int out_size)
{
    const float* x  = (const float*)d_in[0];
    const float* Wq = (const float*)d_in[1];
    const float* bq = (const float*)d_in[2];
    const float* Wk = (const float*)d_in[3];
    const float* bk = (const float*)d_in[4];
    const float* Wv = (const float*)d_in[5];
    const float* bv = (const float*)d_in[6];
    const float* Wo = (const float*)d_in[7];
    const float* bo = (const float*)d_in[8];
    float* out = (float*)d_out;

    static bool init = false;
    if (!init) {
        cudaFuncSetAttribute(k_fused, cudaFuncAttributeMaxDynamicSharedMemorySize, FUSED_SMEM);
        init = true;
    }

    dim3 grid(NH, 32);   // 128 CTAs — all co-resident (1/SM, 148 SMs)
    k_fused<<<grid, 256, FUSED_SMEM>>>(x, Wq, Wk, Wv, Wo, bq, bk, bv, bo, out);
}